// round 15
// baseline (speedup 1.0000x reference)
#include <cuda_runtime.h>
#include <cuda_fp16.h>

// Trilinear interpolation: fp16 channel-last scratch + 2-lane 256-bit gather,
// warp-cooperative coords, no early exit (full warps, guarded stores).
//   input  d_in[0]: float32 [16, 128, 128, 128]  (C, z, y, x)
//   coords d_in[1]: float32 [1000000, 3] in [-1, 1]
//   out    d_out  : float32 [16, 1000000]

#define GS        128
#define NCH       16
#define NSPATIAL  (GS * GS * GS)
#define PAD_CELLS (GS * GS + GS + 1)   // +1 plane/row/cell for unclamped +1 corners

// fp16 scratch, zero-initialized (pad region must read as 0.0)
__device__ __align__(128) __half g_trans[(size_t)NCH * (NSPATIAL + PAD_CELLS)];

struct U8 { unsigned r0, r1, r2, r3, r4, r5, r6, r7; };

__device__ __forceinline__ U8 ldg256_evict_last(const void* p) {
    U8 v;
    asm volatile("ld.global.L2::evict_last.v8.u32 {%0,%1,%2,%3,%4,%5,%6,%7}, [%8];"
                 : "=r"(v.r0), "=r"(v.r1), "=r"(v.r2), "=r"(v.r3),
                   "=r"(v.r4), "=r"(v.r5), "=r"(v.r6), "=r"(v.r7)
                 : "l"(p));
    return v;
}

__device__ __forceinline__ void stg256_evict_last(void* p, unsigned long long a,
                                                  unsigned long long b,
                                                  unsigned long long c,
                                                  unsigned long long d) {
    asm volatile("st.global.L2::evict_last.v4.u64 [%0], {%1,%2,%3,%4};"
                 :: "l"(p), "l"(a), "l"(b), "l"(c), "l"(d) : "memory");
}

__global__ void __launch_bounds__(256) transpose_kernel(const float* __restrict__ in) {
    int idx = blockIdx.x * blockDim.x + threadIdx.x;
    if (idx >= NSPATIAL) return;
    __half2 v[NCH / 2];
#pragma unroll
    for (int c = 0; c < NCH; c += 2) {
        float a = __ldcs(in + (size_t)c * NSPATIAL + idx);        // streaming reads
        float b = __ldcs(in + (size_t)(c + 1) * NSPATIAL + idx);
        v[c / 2] = __floats2half2_rn(a, b);
    }
    const unsigned long long* s = reinterpret_cast<const unsigned long long*>(v);
    // grid born L2-resident with retention priority (single 32B store)
    stg256_evict_last(g_trans + (size_t)idx * NCH, s[0], s[1], s[2], s[3]);
}

__global__ void __launch_bounds__(256, 5) gather_kernel(const float* __restrict__ coords,
                                                        float* __restrict__ out,
                                                        int N) {
    int tid   = threadIdx.x;
    int wlane = tid & 31;
    int warp  = (blockIdx.x * blockDim.x + tid) >> 5;
    int pbase = warp * 16;                 // warp covers 16 consecutive points
    int g     = wlane >> 1;                // this lane's point within the warp
    int lane  = wlane & 1;                 // x-corner this lane owns
    int n     = pbase + g;

    // ---- warp-cooperative coords: 16 pts x 3 floats = 48 floats, 2 LDGs ----
    long long cb   = (long long)pbase * 3;
    long long maxi = (long long)N * 3 - 1;
    long long i1 = cb + wlane;            if (i1 > maxi) i1 = maxi;
    long long i2 = cb + 32 + (wlane & 15); if (i2 > maxi) i2 = maxi;
    float cva = __ldcs(coords + i1);
    float cvb = __ldcs(coords + i2);

    float c[3];
#pragma unroll
    for (int k = 0; k < 3; k++) {
        int idx = 3 * g + k;               // 0..47
        float a = __shfl_sync(0xFFFFFFFFu, cva, idx & 31);
        float b = __shfl_sync(0xFFFFFFFFu, cvb, idx & 15);
        c[k] = (idx < 32) ? a : b;
    }

    // map [-1,1] -> [0,127], clamp in fp; +1 corners may land in the zero pad
    // but always carry weight exactly 0 there.
    float f0 = fminf(fmaxf(fmaf(c[0], 63.5f, 63.5f), 0.0f), 127.0f);
    float f1 = fminf(fmaxf(fmaf(c[1], 63.5f, 63.5f), 0.0f), 127.0f);
    float f2 = fminf(fmaxf(fmaf(c[2], 63.5f, 63.5f), 0.0f), 127.0f);

    float fl0 = floorf(f0), fl1 = floorf(f1), fl2 = floorf(f2);
    float r0 = f0 - fl0, r1 = f1 - fl1, r2 = f2 - fl2;

    int cell00 = (((int)fl0 * GS + (int)fl1) * GS + (int)fl2);

    float wxl = lane ? r2 : (1.0f - r2);          // this lane's x weight
    float wzy[4];
    wzy[0] = (1.0f - r0) * (1.0f - r1) * wxl;     // z0 y0
    wzy[1] = (1.0f - r0) * r1 * wxl;              // z0 y1
    wzy[2] = r0 * (1.0f - r1) * wxl;              // z1 y0
    wzy[3] = r0 * r1 * wxl;                       // z1 y1

    // lane's cell: x0 (+0) or x0+1 (+32 B); lanes 2g,2g+1 form 64 B contiguous
    const char* base = reinterpret_cast<const char*>(g_trans)
                     + (size_t)cell00 * 32 + (unsigned)lane * 32;

    float acc[16];
#pragma unroll
    for (int k = 0; k < 16; k++) acc[k] = 0.0f;

#pragma unroll
    for (int k = 0; k < 4; k++) {
        float w = wzy[k];
        U8 raw = ldg256_evict_last(
            base + ((size_t)(k >> 1) * (GS * GS) + (size_t)(k & 1) * GS) * 32);
        const unsigned* r = &raw.r0;
#pragma unroll
        for (int j = 0; j < 8; j++) {
            float2 v = __half22float2(*reinterpret_cast<const __half2*>(&r[j]));
            acc[2 * j + 0] = fmaf(w, v.x, acc[2 * j + 0]);
            acc[2 * j + 1] = fmaf(w, v.y, acc[2 * j + 1]);
        }
    }

    // combine x0/x1 partials. lane0 stores ch0-7, lane1 stores ch8-15;
    // each lane sends the half its partner stores, receives its own half.
    float fin[8];
#pragma unroll
    for (int j = 0; j < 8; j++) {
        float send = lane ? acc[j] : acc[8 + j];
        float keep = lane ? acc[8 + j] : acc[j];
        fin[j] = keep + __shfl_xor_sync(0xFFFFFFFFu, send, 1);
    }

    if (n < N) {
        int chbase = lane * 8;
        size_t nn = (size_t)n;
#pragma unroll
        for (int j = 0; j < 8; j++) {
            __stcs(out + (size_t)(chbase + j) * N + nn, fin[j]);
        }
    }
}

extern "C" void kernel_launch(void* const* d_in, const int* in_sizes, int n_in,
                              void* d_out, int out_size) {
    const float* input  = (const float*)d_in[0];
    const float* coords = (const float*)d_in[1];
    float* out = (float*)d_out;
    int N = in_sizes[1] / 3;

    transpose_kernel<<<(NSPATIAL + 255) / 256, 256>>>(input);

    long long threads = 2LL * N;
    int blocks = (int)((threads + 255) / 256);
    gather_kernel<<<blocks, 256>>>(coords, out, N);
}

// round 16
// speedup vs baseline: 1.0545x; 1.0545x over previous
#include <cuda_runtime.h>
#include <cuda_fp16.h>

// Trilinear interpolation: fp16 channel-last scratch + 4-lane pair gather,
// warp-cooperative coords + HFMA2 fp16 accumulation (fp32 cross-lane combine).
//   input  d_in[0]: float32 [16, 128, 128, 128]  (C, z, y, x)
//   coords d_in[1]: float32 [1000000, 3] in [-1, 1]
//   out    d_out  : float32 [16, 1000000]

#define GS        128
#define NCH       16
#define NSPATIAL  (GS * GS * GS)
#define PAD_CELLS (GS * GS + GS + 1)   // +1 plane/row/cell for unclamped +1 corners

// fp16 scratch, zero-initialized (pad region must read as 0.0)
__device__ __align__(128) __half g_trans[(size_t)NCH * (NSPATIAL + PAD_CELLS)];

__device__ __forceinline__ unsigned long long make_evict_last_policy() {
    unsigned long long pol;
    asm volatile("createpolicy.fractional.L2::evict_last.b64 %0, 1.0;" : "=l"(pol));
    return pol;
}

__device__ __forceinline__ uint4 ldg_hint(const void* p, unsigned long long pol) {
    uint4 v;
    asm volatile("ld.global.L2::cache_hint.v4.u32 {%0,%1,%2,%3}, [%4], %5;"
                 : "=r"(v.x), "=r"(v.y), "=r"(v.z), "=r"(v.w)
                 : "l"(p), "l"(pol));
    return v;
}

__device__ __forceinline__ void stg256_evict_last(void* p, unsigned long long a,
                                                  unsigned long long b,
                                                  unsigned long long c,
                                                  unsigned long long d) {
    asm volatile("st.global.L2::evict_last.v4.u64 [%0], {%1,%2,%3,%4};"
                 :: "l"(p), "l"(a), "l"(b), "l"(c), "l"(d) : "memory");
}

__global__ void __launch_bounds__(256) transpose_kernel(const float* __restrict__ in) {
    int idx = blockIdx.x * blockDim.x + threadIdx.x;
    if (idx >= NSPATIAL) return;
    __half2 v[NCH / 2];
#pragma unroll
    for (int c = 0; c < NCH; c += 2) {
        float a = __ldcs(in + (size_t)c * NSPATIAL + idx);        // streaming reads
        float b = __ldcs(in + (size_t)(c + 1) * NSPATIAL + idx);
        v[c / 2] = __floats2half2_rn(a, b);
    }
    const unsigned long long* s = reinterpret_cast<const unsigned long long*>(v);
    // grid born L2-resident with retention priority (single 32B store)
    stg256_evict_last(g_trans + (size_t)idx * NCH, s[0], s[1], s[2], s[3]);
}

__global__ void __launch_bounds__(256, 8) gather_kernel(const float* __restrict__ coords,
                                                        float* __restrict__ out,
                                                        int N) {
    int t    = blockIdx.x * blockDim.x + threadIdx.x;
    int n    = t >> 2;        // point index
    int lane = t & 3;         // 0: x0/ch0-7  1: x0/ch8-15  2: x1/ch0-7  3: x1/ch8-15
    if (n >= N) return;

    unsigned long long pol = make_evict_last_policy();
    unsigned mask = __activemask();   // active lanes form a prefix of the warp

    // ---- warp-cooperative coords load: one LDG (96 B) + 3 shuffles ----
    int wlane = threadIdx.x & 31;
    int pbase = n - (wlane >> 2);             // warp's first point
    float cv = 0.0f;
    if (wlane < 24) {
        long long idx = (long long)pbase * 3 + wlane;
        long long maxi = (long long)N * 3 - 1;
        cv = __ldcs(coords + (idx < maxi ? idx : maxi));
    }
    int g  = wlane >> 2;                      // this lane's point-group within warp
    float c0 = __shfl_sync(mask, cv, 3 * g + 0);
    float c1 = __shfl_sync(mask, cv, 3 * g + 1);
    float c2 = __shfl_sync(mask, cv, 3 * g + 2);

    // map [-1,1] -> [0,127], clamp in fp; +1 corners may land in the zero pad
    // but always carry weight exactly 0 there.
    float f0 = fminf(fmaxf(fmaf(c0, 63.5f, 63.5f), 0.0f), 127.0f);
    float f1 = fminf(fmaxf(fmaf(c1, 63.5f, 63.5f), 0.0f), 127.0f);
    float f2 = fminf(fmaxf(fmaf(c2, 63.5f, 63.5f), 0.0f), 127.0f);

    float fl0 = floorf(f0), fl1 = floorf(f1), fl2 = floorf(f2);
    float r0 = f0 - fl0, r1 = f1 - fl1, r2 = f2 - fl2;

    int cell00 = (((int)fl0 * GS + (int)fl1) * GS + (int)fl2);

    float wz[2] = {1.0f - r0, r0};
    float wy[2] = {1.0f - r1, r1};
    float wxl   = (lane < 2) ? (1.0f - r2) : r2;   // this lane's x-corner weight

    const char* base = reinterpret_cast<const char*>(g_trans)
                     + (size_t)cell00 * 32 + lane * 16;

    // fp16 packed accumulators: 4 x half2 = this lane's 8 channels
    __half2 acc[4];
#pragma unroll
    for (int k = 0; k < 4; k++) acc[k] = __half2half2(__float2half_rn(0.0f));

#pragma unroll
    for (int a = 0; a < 2; a++) {
#pragma unroll
        for (int b = 0; b < 2; b++) {
            float w = wz[a] * wy[b] * wxl;
            __half2 w2 = __float2half2_rn(w);
            uint4 raw = ldg_hint(
                base + ((size_t)a * (GS * GS) + (size_t)b * GS) * 32, pol);
            const __half2* hv = reinterpret_cast<const __half2*>(&raw);
            acc[0] = __hfma2(hv[0], w2, acc[0]);
            acc[1] = __hfma2(hv[1], w2, acc[1]);
            acc[2] = __hfma2(hv[2], w2, acc[2]);
            acc[3] = __hfma2(hv[3], w2, acc[3]);
        }
    }

    // combine x0/x1 partials in fp32: shuffle packed half2 (4 x u32), convert,
    // add. Partner lane = lane^2 (same point, guaranteed active).
    float fin[8];
#pragma unroll
    for (int j = 0; j < 4; j++) {
        unsigned mine  = *reinterpret_cast<unsigned*>(&acc[j]);
        unsigned other = __shfl_xor_sync(mask, mine, 2);
        float2 a = __half22float2(*reinterpret_cast<__half2*>(&mine));
        float2 b = __half22float2(*reinterpret_cast<__half2*>(&other));
        fin[2 * j + 0] = a.x + b.x;
        fin[2 * j + 1] = a.y + b.y;
    }

    // lanes 0,2 hold final ch0-7; lanes 1,3 hold final ch8-15.
    //   lane0: ch0-3  lane2: ch4-7  lane1: ch8-11  lane3: ch12-15
    int sel    = lane >> 1;
    int chbase = (lane & 1) * 8 + sel * 4;
    size_t nn  = (size_t)n;
#pragma unroll
    for (int j = 0; j < 4; j++) {
        __stcs(out + (size_t)(chbase + j) * N + nn, fin[sel * 4 + j]);
    }
}

extern "C" void kernel_launch(void* const* d_in, const int* in_sizes, int n_in,
                              void* d_out, int out_size) {
    const float* input  = (const float*)d_in[0];
    const float* coords = (const float*)d_in[1];
    float* out = (float*)d_out;
    int N = in_sizes[1] / 3;

    transpose_kernel<<<(NSPATIAL + 255) / 256, 256>>>(input);

    long long threads = 4LL * N;
    int blocks = (int)((threads + 255) / 256);
    gather_kernel<<<blocks, 256>>>(coords, out, N);
}